// round 1
// baseline (speedup 1.0000x reference)
#include <cuda_runtime.h>

// TrueHigherOrderAttention — degenerate-mask reduction.
//
// The reference's sparse-causal mask requires j<=i & j>=i (=> j==i) and
// k<=j & k>=i (=> k==i), so softmax over the (j,k) plane is an exact one-hot
// at (i,i,i) (masked logits are float32.min; exp underflows to 0 exactly).
// Hence:  out = ((x @ Wv1^T) .* (x @ Wv2^T)) @ Wc^T
// q/k projections are dead code.

constexpr int T  = 256;
constexpr int C  = 512;
constexpr int KC = 64;   // K chunk
constexpr int PAD = 68;  // smem row stride in floats (16B-aligned, low-conflict)

__device__ float g_tmp[T * C];

// Computes OUT = (X @ W1^T) [ .* (X @ W2^T) if DUAL ]
// X: [M x C] row-major, W: [C x C] row-major (output col n uses W row n).
// Tile: 32 (rows of X) x 32 (rows of W). 256 threads, 2x2 microtile each.
template <bool DUAL>
__global__ __launch_bounds__(256, 1)
void gemm_prod_kernel(const float* __restrict__ X,
                      const float* __restrict__ W1,
                      const float* __restrict__ W2,
                      float* __restrict__ OUT)
{
    __shared__ float xs [32 * PAD];
    __shared__ float w1s[32 * PAD];
    __shared__ float w2s[DUAL ? 32 * PAD : 4];

    const int i0  = blockIdx.x * 32;   // row block in [0, T)
    const int n0  = blockIdx.y * 32;   // col block in [0, C)
    const int tid = threadIdx.x;
    const int tx  = tid & 15;          // 0..15 -> output cols {tx, tx+16}
    const int ty  = tid >> 4;          // 0..15 -> output rows {ty, ty+16}

    float p00 = 0.f, p01 = 0.f, p10 = 0.f, p11 = 0.f;
    float q00 = 0.f, q01 = 0.f, q10 = 0.f, q11 = 0.f;

    for (int kc = 0; kc < C; kc += KC) {
        __syncthreads();
        // Cooperative load: each tile is 32 rows x 64 floats = 512 float4;
        // 256 threads -> 2 float4 per thread per tile. Global offsets are
        // multiples of 4 floats => 16B aligned.
        #pragma unroll
        for (int it = 0; it < 2; it++) {
            int qq  = tid + it * 256;
            int row = qq >> 4;          // 0..31
            int c4  = (qq & 15) * 4;    // 0..60
            *(float4*)&xs [row * PAD + c4] =
                *(const float4*)&X [(i0 + row) * C + kc + c4];
            *(float4*)&w1s[row * PAD + c4] =
                *(const float4*)&W1[(n0 + row) * C + kc + c4];
            if (DUAL)
                *(float4*)&w2s[row * PAD + c4] =
                    *(const float4*)&W2[(n0 + row) * C + kc + c4];
        }
        __syncthreads();

        #pragma unroll
        for (int kk = 0; kk < KC; kk++) {
            float a0 = xs[ ty       * PAD + kk];
            float a1 = xs[(ty + 16) * PAD + kk];
            float b0 = w1s[ tx       * PAD + kk];
            float b1 = w1s[(tx + 16) * PAD + kk];
            p00 += a0 * b0; p01 += a0 * b1;
            p10 += a1 * b0; p11 += a1 * b1;
            if (DUAL) {
                float c0 = w2s[ tx       * PAD + kk];
                float c1 = w2s[(tx + 16) * PAD + kk];
                q00 += a0 * c0; q01 += a0 * c1;
                q10 += a1 * c0; q11 += a1 * c1;
            }
        }
    }

    const float r00 = DUAL ? p00 * q00 : p00;
    const float r01 = DUAL ? p01 * q01 : p01;
    const float r10 = DUAL ? p10 * q10 : p10;
    const float r11 = DUAL ? p11 * q11 : p11;

    OUT[(i0 + ty     ) * C + n0 + tx     ] = r00;
    OUT[(i0 + ty     ) * C + n0 + tx + 16] = r01;
    OUT[(i0 + ty + 16) * C + n0 + tx     ] = r10;
    OUT[(i0 + ty + 16) * C + n0 + tx + 16] = r11;
}

// Stage 1: g_tmp = (x @ Wv1^T) .* (x @ Wv2^T)
__global__ __launch_bounds__(256, 1)
void stage1_kernel(const float* __restrict__ x,
                   const float* __restrict__ Wv1,
                   const float* __restrict__ Wv2)
{
    // thin wrapper so g_tmp is referenced device-side (no symbol lookup on host)
    // — inline the templated body by tail-calling is not possible; instead we
    // duplicate via the template with OUT = g_tmp.
    // (Implemented below via direct call.)
    // This kernel body is unused; see launch of gemm_prod_kernel with g_tmp.
}

extern "C" void kernel_launch(void* const* d_in, const int* in_sizes, int n_in,
                              void* d_out, int out_size)
{
    // metadata order: x, Wq, Wk1, Wk2, Wv1, Wv2, Wc
    const float* x   = (const float*)d_in[0];
    const float* Wv1 = (const float*)d_in[4];
    const float* Wv2 = (const float*)d_in[5];
    const float* Wc  = (const float*)d_in[6];
    float* out = (float*)d_out;

    // Resolve the device scratch symbol once per call (no allocation, no sync,
    // graph-capture safe: pure address query).
    float* tmp = nullptr;
    cudaGetSymbolAddress((void**)&tmp, g_tmp);

    dim3 grid(T / 32, C / 32);   // 8 x 16 = 128 CTAs
    gemm_prod_kernel<true ><<<grid, 256>>>(x,   Wv1, Wv2,     tmp);
    gemm_prod_kernel<false><<<grid, 256>>>(tmp, Wc,  nullptr, out);
}